// round 16
// baseline (speedup 1.0000x reference)
#include <cuda_runtime.h>
#include <math.h>

#define B 16
#define T 2048
#define D 768
#define D4 192          // D/4 float4 lanes
#define A 5
#define NSEG1 32        // t-segments for mean partials (64 t each)
#define NSEG 32         // t-segments for agent_v partials (64 t each)
#define TSEG 64
#define NSKT 256        // skt blocks per b (8 t each)
#define ETILE 64        // epilogue t rows per CTA

// ---- scratch (device globals; no allocation) ----
__device__ float4 g_mpart[B][NSEG1][D4];       // 1.5 MB (L2-hot)
__device__ float4 g_m[B][D4];                  // 48 KB
__device__ float  g_w[B][A][T];                // 640 KB unnormalized weights
__device__ float  g_wsp[B][A][NSKT];           // per-block weight sums
__device__ float4 g_avpart[B][NSEG][A][D4];    // 7.9 MB (L2-hot, unnormalized)
__device__ float4 g_av[B][A][D4];              // 240 KB

// ---------------------------------------------------------------
// Kernel 1: masked-sum partials of q. grid (NSEG1, B) = 512, block 192.
// Batches of 8 keep 8 LDG.128 in flight; mask==0 rows predicated off.
__global__ void __launch_bounds__(192, 4)
k_mean_part(const float4* __restrict__ q, const int* __restrict__ mask) {
    cudaTriggerProgrammaticLaunchCompletion();
    const int seg = blockIdx.x, b = blockIdx.y;
    const int tid = threadIdx.x;               // d4 lane
    const int t0 = seg * (T / NSEG1);
    __shared__ int smask[T / NSEG1];
    if (tid < T / NSEG1) smask[tid] = mask[b * T + t0 + tid];
    __syncthreads();
    const float4* qb = q + ((size_t)b * T + t0) * D4 + tid;
    float4 acc = make_float4(0.f, 0.f, 0.f, 0.f);
    for (int tt = 0; tt < T / NSEG1; tt += 8) {
        float4 vv[8];
        #pragma unroll
        for (int j = 0; j < 8; ++j) {
            if (smask[tt + j]) vv[j] = qb[(size_t)(tt + j) * D4];
            else               vv[j] = make_float4(0.f, 0.f, 0.f, 0.f);
        }
        #pragma unroll
        for (int j = 0; j < 8; ++j) {
            acc.x += vv[j].x; acc.y += vv[j].y;
            acc.z += vv[j].z; acc.w += vv[j].w;
        }
    }
    g_mpart[b][seg][tid] = acc;
}

// Kernel 1b: finish mean (divide by T, torch semantics). B*D4 threads.
__global__ void k_mean_fin() {
    cudaGridDependencySynchronize();
    cudaTriggerProgrammaticLaunchCompletion();
    int i = blockIdx.x * 256 + threadIdx.x;
    if (i >= B * D4) return;
    int b = i / D4, d = i % D4;
    float4 acc = make_float4(0.f, 0.f, 0.f, 0.f);
    #pragma unroll
    for (int s = 0; s < NSEG1; ++s) {
        float4 v = g_mpart[b][s][d];
        acc.x += v.x; acc.y += v.y; acc.z += v.z; acc.w += v.w;
    }
    const float inv = 1.0f / (float)T;
    acc.x *= inv; acc.y *= inv; acc.z *= inv; acc.w *= inv;
    g_m[b][d] = acc;
}

// ---------------------------------------------------------------
// Kernel 2: s[b,t] = k[b,t,:].m[b,:]; emit UNNORMALIZED weights
// e[a,t] = exp(s_t + b1[a,t]) and per-block weight sums.
// PDL: k rows prefetched into registers BEFORE syncing on g_m.
// grid (NSKT, B), block 256 (8 warps, one t each).
__global__ void k_skt(const float4* __restrict__ k,
                      const float* __restrict__ b1) {
    const int b = blockIdx.y;
    const int warp = threadIdx.x >> 5;
    const int lane = threadIdx.x & 31;
    const int t0 = blockIdx.x * 8;
    const int t = t0 + warp;
    const float4* kr = k + ((size_t)b * T + t) * D4;
    float4 kv[D4 / 32];                        // 6 x LDG.128 prologue
    #pragma unroll
    for (int i = 0; i < D4 / 32; ++i) kv[i] = kr[lane + i * 32];

    cudaGridDependencySynchronize();           // g_m ready
    cudaTriggerProgrammaticLaunchCompletion();

    __shared__ float4 sm[D4];
    __shared__ float ss[8];
    __shared__ float se[8][8];                 // [t][a] padded
    if (threadIdx.x < D4) sm[threadIdx.x] = g_m[b][threadIdx.x];
    __syncthreads();
    float acc = 0.f;
    #pragma unroll
    for (int i = 0; i < D4 / 32; ++i) {
        float4 mv = sm[lane + i * 32];
        acc += kv[i].x * mv.x + kv[i].y * mv.y + kv[i].z * mv.z + kv[i].w * mv.w;
    }
    #pragma unroll
    for (int o = 16; o; o >>= 1) acc += __shfl_down_sync(0xffffffffu, acc, o);
    if (lane == 0) ss[warp] = acc;
    __syncthreads();
    if (threadIdx.x < A * 8) {
        const int a = threadIdx.x >> 3, j = threadIdx.x & 7;
        float e = expf(ss[j] + b1[a * T + t0 + j]);
        g_w[b][a][t0 + j] = e;
        se[j][a] = e;
    }
    __syncthreads();
    if (threadIdx.x < A) {
        const int a = threadIdx.x;
        float sum = 0.f;
        #pragma unroll
        for (int j = 0; j < 8; ++j) sum += se[j][a];
        g_wsp[b][a][blockIdx.x] = sum;
    }
}

// ---------------------------------------------------------------
// Kernel 3: agent_v partials — pure v stream, weights from L2-hot g_w.
// PDL: batch 0 of v prefetched before syncing on g_w.
// grid (NSEG, B) = 512 blocks, block 192. Reads v once (100MB), MLP 8.
__global__ void __launch_bounds__(192, 4)
k_av_part(const float4* __restrict__ v) {
    const int seg = blockIdx.x, b = blockIdx.y;
    const int tid = threadIdx.x;
    const int t0 = seg * TSEG;
    const float4* vb = v + ((size_t)b * T + t0) * D4 + tid;

    float4 vv[8];                               // prologue: batch 0
    #pragma unroll
    for (int j = 0; j < 8; ++j) vv[j] = vb[(size_t)j * D4];

    cudaGridDependencySynchronize();            // g_w ready
    cudaTriggerProgrammaticLaunchCompletion();

    __shared__ __align__(16) float sw[TSEG][8];   // [t][a] padded
    for (int i = tid; i < TSEG * A; i += 192) {
        int a = i / TSEG, tt = i % TSEG;           // coalesced g_w reads
        sw[tt][a] = g_w[b][a][t0 + tt];
    }
    __syncthreads();

    float4 a0 = make_float4(0,0,0,0), a1 = a0, a2 = a0, a3 = a0, a4 = a0;
    for (int tt = 0; tt < TSEG; tt += 8) {
        if (tt) {                                  // batches 1..7 load here
            #pragma unroll
            for (int j = 0; j < 8; ++j) vv[j] = vb[(size_t)(tt + j) * D4];
        }
        #pragma unroll
        for (int j = 0; j < 8; ++j) {
            float4 wv = *(const float4*)&sw[tt + j][0];  // w0..w3 (LDS.128)
            float  w4 = sw[tt + j][4];
            a0.x += wv.x*vv[j].x; a0.y += wv.x*vv[j].y; a0.z += wv.x*vv[j].z; a0.w += wv.x*vv[j].w;
            a1.x += wv.y*vv[j].x; a1.y += wv.y*vv[j].y; a1.z += wv.y*vv[j].z; a1.w += wv.y*vv[j].w;
            a2.x += wv.z*vv[j].x; a2.y += wv.z*vv[j].y; a2.z += wv.z*vv[j].z; a2.w += wv.z*vv[j].w;
            a3.x += wv.w*vv[j].x; a3.y += wv.w*vv[j].y; a3.z += wv.w*vv[j].z; a3.w += wv.w*vv[j].w;
            a4.x += w4  *vv[j].x; a4.y += w4  *vv[j].y; a4.z += w4  *vv[j].z; a4.w += w4  *vv[j].w;
        }
    }
    g_avpart[b][seg][0][tid] = a0;
    g_avpart[b][seg][1][tid] = a1;
    g_avpart[b][seg][2][tid] = a2;
    g_avpart[b][seg][3][tid] = a3;
    g_avpart[b][seg][4][tid] = a4;
}

// ---------------------------------------------------------------
// Kernel 3b: reduce agent_v partials (L2-hot) + normalize by global sum.
// PDL: g_wsp (skt output — transitively complete) reduced in prologue.
// grid (A, B), block 192.
__global__ void k_av_fin() {
    const int a = blockIdx.x, b = blockIdx.y;
    const int tid = threadIdx.x;
    __shared__ float sInvS;
    if (tid < 32) {                              // prologue: weight sum
        float s = 0.f;
        #pragma unroll
        for (int j = 0; j < NSKT / 32; ++j) s += g_wsp[b][a][tid + j * 32];
        #pragma unroll
        for (int o = 16; o; o >>= 1) s += __shfl_down_sync(0xffffffffu, s, o);
        if (tid == 0) sInvS = 1.0f / s;
    }
    cudaGridDependencySynchronize();             // g_avpart ready
    cudaTriggerProgrammaticLaunchCompletion();
    float4 acc = make_float4(0.f, 0.f, 0.f, 0.f);
    #pragma unroll
    for (int s = 0; s < NSEG; ++s) {
        float4 p = g_avpart[b][s][a][tid];
        acc.x += p.x; acc.y += p.y; acc.z += p.z; acc.w += p.w;
    }
    __syncthreads();
    const float inv = sInvS;
    g_av[b][a][tid] = make_float4(acc.x * inv, acc.y * inv, acc.z * inv, acc.w * inv);
}

// ---------------------------------------------------------------
// Kernel 4: epilogue with inline stage-2 softmax, 64 t rows per CTA.
// PDL: b2 softmax (pure input) computed before syncing on g_av.
// x[b,t,d] = sum_a softmax_a(b2[t,:])[a] * agent_v[b,a,d]
// grid (T/ETILE, B) = 512 blocks, block 192. Writes x once (100MB).
__global__ void k_epilogue(const float* __restrict__ b2,
                           float4* __restrict__ out) {
    const int tb = blockIdx.x, b = blockIdx.y;
    const int tid = threadIdx.x;
    const int t0 = tb * ETILE;
    __shared__ __align__(16) float sp[ETILE][8];   // padded
    if (tid < ETILE) {                              // prologue
        int t = t0 + tid;
        float vv[A];
        float mx = -1e30f;
        #pragma unroll
        for (int a = 0; a < A; ++a) { vv[a] = b2[t * A + a]; mx = fmaxf(mx, vv[a]); }
        float sum = 0.f;
        #pragma unroll
        for (int a = 0; a < A; ++a) { vv[a] = expf(vv[a] - mx); sum += vv[a]; }
        float inv = 1.0f / sum;
        #pragma unroll
        for (int a = 0; a < A; ++a) sp[tid][a] = vv[a] * inv;
    }
    cudaGridDependencySynchronize();             // g_av ready
    float4 av0 = g_av[b][0][tid], av1 = g_av[b][1][tid], av2 = g_av[b][2][tid],
           av3 = g_av[b][3][tid], av4 = g_av[b][4][tid];
    __syncthreads();
    float4* ob = out + ((size_t)b * T + t0) * D4 + tid;
    #pragma unroll 8
    for (int tt = 0; tt < ETILE; ++tt) {
        float4 pv = *(const float4*)&sp[tt][0];
        float  p4 = sp[tt][4];
        float4 r;
        r.x = pv.x*av0.x + pv.y*av1.x + pv.z*av2.x + pv.w*av3.x + p4*av4.x;
        r.y = pv.x*av0.y + pv.y*av1.y + pv.z*av2.y + pv.w*av3.y + p4*av4.y;
        r.z = pv.x*av0.z + pv.y*av1.z + pv.z*av2.z + pv.w*av3.z + p4*av4.z;
        r.w = pv.x*av0.w + pv.y*av1.w + pv.z*av2.w + pv.w*av3.w + p4*av4.w;
        ob[(size_t)tt * D4] = r;
    }
}

// ---------------------------------------------------------------
template <typename... Args>
static void launch_pdl(void (*kern)(Args...), dim3 grid, dim3 block,
                       bool pdl, Args... args) {
    cudaLaunchConfig_t cfg = {};
    cfg.gridDim = grid;
    cfg.blockDim = block;
    cfg.dynamicSmemBytes = 0;
    cfg.stream = 0;                              // legacy default stream
    cudaLaunchAttribute attr[1];
    attr[0].id = cudaLaunchAttributeProgrammaticStreamSerialization;
    attr[0].val.programmaticStreamSerializationAllowed = 1;
    cfg.attrs = attr;
    cfg.numAttrs = pdl ? 1 : 0;
    cudaLaunchKernelEx(&cfg, kern, args...);
}

extern "C" void kernel_launch(void* const* d_in, const int* in_sizes, int n_in,
                              void* d_out, int out_size) {
    const float* qkv  = (const float*)d_in[0];        // [3,B,T,D]
    const int*   mask = (const int*)d_in[1];          // [B,T]
    const float* b1   = (const float*)d_in[2];        // [A,T]
    const float* b2   = (const float*)d_in[3];        // [T,A]

    const float4* q = (const float4*)qkv;
    const float4* k = (const float4*)(qkv + (size_t)B * T * D);
    const float4* v = (const float4*)(qkv + 2 * (size_t)B * T * D);

    launch_pdl(k_mean_part, dim3(NSEG1, B), dim3(192), false, q, mask);
    launch_pdl(k_mean_fin, dim3((B * D4 + 255) / 256), dim3(256), true);
    launch_pdl(k_skt, dim3(NSKT, B), dim3(256), true, k, b1);
    launch_pdl(k_av_part, dim3(NSEG, B), dim3(192), true, v);
    launch_pdl(k_av_fin, dim3(A, B), dim3(192), true);
    launch_pdl(k_epilogue, dim3(T / ETILE, B), dim3(192), true, b2,
               (float4*)d_out);
}

// round 17
// speedup vs baseline: 1.0236x; 1.0236x over previous
#include <cuda_runtime.h>
#include <math.h>

#define B 16
#define T 2048
#define D 768
#define D4 192          // D/4 float4 lanes
#define A 5
#define NSEG1 32        // t-segments for mean partials (64 t each)
#define NSEG 32         // t-segments for agent_v partials (64 t each)
#define TSEG 64
#define NSKT 256        // skt blocks per b (8 t each)

// ---- scratch (device globals; no allocation) ----
__device__ float4 g_mpart[B][NSEG1][D4];       // 1.5 MB (L2-hot)
__device__ float4 g_m[B][D4];                  // 48 KB
__device__ float  g_w[B][A][T];                // 640 KB unnormalized weights
__device__ float  g_wsp[B][A][NSKT];           // per-block weight sums
__device__ float4 g_avpart[B][NSEG][A][D4];    // 7.9 MB (L2-hot, unnormalized)
__device__ float4 g_av[B][A][D4];              // 240 KB

// ---------------------------------------------------------------
// Kernel 1: masked-sum partials of q. grid (NSEG1, B) = 512, block 192.
// Batches of 8 keep 8 LDG.128 in flight; mask==0 rows predicated off.
__global__ void __launch_bounds__(192, 4)
k_mean_part(const float4* __restrict__ q, const int* __restrict__ mask) {
    cudaTriggerProgrammaticLaunchCompletion();
    const int seg = blockIdx.x, b = blockIdx.y;
    const int tid = threadIdx.x;               // d4 lane
    const int t0 = seg * (T / NSEG1);
    __shared__ int smask[T / NSEG1];
    if (tid < T / NSEG1) smask[tid] = mask[b * T + t0 + tid];
    __syncthreads();
    const float4* qb = q + ((size_t)b * T + t0) * D4 + tid;
    float4 acc = make_float4(0.f, 0.f, 0.f, 0.f);
    for (int tt = 0; tt < T / NSEG1; tt += 8) {
        float4 vv[8];
        #pragma unroll
        for (int j = 0; j < 8; ++j) {
            if (smask[tt + j]) vv[j] = qb[(size_t)(tt + j) * D4];
            else               vv[j] = make_float4(0.f, 0.f, 0.f, 0.f);
        }
        #pragma unroll
        for (int j = 0; j < 8; ++j) {
            acc.x += vv[j].x; acc.y += vv[j].y;
            acc.z += vv[j].z; acc.w += vv[j].w;
        }
    }
    g_mpart[b][seg][tid] = acc;
}

// Kernel 1b: finish mean (divide by T, torch semantics). B*D4 threads.
__global__ void k_mean_fin() {
    cudaGridDependencySynchronize();
    cudaTriggerProgrammaticLaunchCompletion();
    int i = blockIdx.x * 256 + threadIdx.x;
    if (i >= B * D4) return;
    int b = i / D4, d = i % D4;
    float4 acc = make_float4(0.f, 0.f, 0.f, 0.f);
    #pragma unroll
    for (int s = 0; s < NSEG1; ++s) {
        float4 v = g_mpart[b][s][d];
        acc.x += v.x; acc.y += v.y; acc.z += v.z; acc.w += v.w;
    }
    const float inv = 1.0f / (float)T;
    acc.x *= inv; acc.y *= inv; acc.z *= inv; acc.w *= inv;
    g_m[b][d] = acc;
}

// ---------------------------------------------------------------
// Kernel 2: s[b,t] = k[b,t,:].m[b,:]; emit UNNORMALIZED weights
// e[a,t] = exp(s_t + b1[a,t]) and per-block weight sums.
// No max-shift needed: |s| ~ O(1) by construction (m has std ~1/64).
// PDL: k rows prefetched into registers BEFORE syncing on g_m.
// grid (NSKT, B), block 256 (8 warps, one t each).
__global__ void k_skt(const float4* __restrict__ k,
                      const float* __restrict__ b1) {
    const int b = blockIdx.y;
    const int warp = threadIdx.x >> 5;
    const int lane = threadIdx.x & 31;
    const int t0 = blockIdx.x * 8;
    const int t = t0 + warp;
    const float4* kr = k + ((size_t)b * T + t) * D4;
    float4 kv[D4 / 32];                        // 6 x LDG.128 prologue
    #pragma unroll
    for (int i = 0; i < D4 / 32; ++i) kv[i] = kr[lane + i * 32];

    cudaGridDependencySynchronize();           // g_m ready
    cudaTriggerProgrammaticLaunchCompletion();

    __shared__ float4 sm[D4];
    __shared__ float ss[8];
    __shared__ float se[8][8];                 // [t][a] padded
    if (threadIdx.x < D4) sm[threadIdx.x] = g_m[b][threadIdx.x];
    __syncthreads();
    float acc = 0.f;
    #pragma unroll
    for (int i = 0; i < D4 / 32; ++i) {
        float4 mv = sm[lane + i * 32];
        acc += kv[i].x * mv.x + kv[i].y * mv.y + kv[i].z * mv.z + kv[i].w * mv.w;
    }
    #pragma unroll
    for (int o = 16; o; o >>= 1) acc += __shfl_down_sync(0xffffffffu, acc, o);
    if (lane == 0) ss[warp] = acc;
    __syncthreads();
    if (threadIdx.x < A * 8) {
        const int a = threadIdx.x >> 3, j = threadIdx.x & 7;
        float e = expf(ss[j] + b1[a * T + t0 + j]);
        g_w[b][a][t0 + j] = e;
        se[j][a] = e;
    }
    __syncthreads();
    if (threadIdx.x < A) {
        const int a = threadIdx.x;
        float sum = 0.f;
        #pragma unroll
        for (int j = 0; j < 8; ++j) sum += se[j][a];
        g_wsp[b][a][blockIdx.x] = sum;
    }
}

// ---------------------------------------------------------------
// Kernel 3: agent_v partials — pure v stream, weights from L2-hot g_w.
// PDL: batch 0 of v prefetched before syncing on g_w.
// grid (NSEG, B) = 512 blocks, block 192. Reads v once (100MB), MLP 8.
__global__ void __launch_bounds__(192, 4)
k_av_part(const float4* __restrict__ v) {
    const int seg = blockIdx.x, b = blockIdx.y;
    const int tid = threadIdx.x;
    const int t0 = seg * TSEG;
    const float4* vb = v + ((size_t)b * T + t0) * D4 + tid;

    float4 vv[8];                               // prologue: batch 0
    #pragma unroll
    for (int j = 0; j < 8; ++j) vv[j] = vb[(size_t)j * D4];

    cudaGridDependencySynchronize();            // g_w ready
    cudaTriggerProgrammaticLaunchCompletion();

    __shared__ __align__(16) float sw[TSEG][8];   // [t][a] padded
    for (int i = tid; i < TSEG * A; i += 192) {
        int a = i / TSEG, tt = i % TSEG;           // coalesced g_w reads
        sw[tt][a] = g_w[b][a][t0 + tt];
    }
    __syncthreads();

    float4 a0 = make_float4(0,0,0,0), a1 = a0, a2 = a0, a3 = a0, a4 = a0;
    for (int tt = 0; tt < TSEG; tt += 8) {
        if (tt) {                                  // batches 1..7 load here
            #pragma unroll
            for (int j = 0; j < 8; ++j) vv[j] = vb[(size_t)(tt + j) * D4];
        }
        #pragma unroll
        for (int j = 0; j < 8; ++j) {
            float4 wv = *(const float4*)&sw[tt + j][0];  // w0..w3 (LDS.128)
            float  w4 = sw[tt + j][4];
            a0.x += wv.x*vv[j].x; a0.y += wv.x*vv[j].y; a0.z += wv.x*vv[j].z; a0.w += wv.x*vv[j].w;
            a1.x += wv.y*vv[j].x; a1.y += wv.y*vv[j].y; a1.z += wv.y*vv[j].z; a1.w += wv.y*vv[j].w;
            a2.x += wv.z*vv[j].x; a2.y += wv.z*vv[j].y; a2.z += wv.z*vv[j].z; a2.w += wv.z*vv[j].w;
            a3.x += wv.w*vv[j].x; a3.y += wv.w*vv[j].y; a3.z += wv.w*vv[j].z; a3.w += wv.w*vv[j].w;
            a4.x += w4  *vv[j].x; a4.y += w4  *vv[j].y; a4.z += w4  *vv[j].z; a4.w += w4  *vv[j].w;
        }
    }
    g_avpart[b][seg][0][tid] = a0;
    g_avpart[b][seg][1][tid] = a1;
    g_avpart[b][seg][2][tid] = a2;
    g_avpart[b][seg][3][tid] = a3;
    g_avpart[b][seg][4][tid] = a4;
}

// ---------------------------------------------------------------
// Kernel 3b: reduce agent_v partials (L2-hot) + normalize by global sum.
// PDL: g_wsp (skt output — transitively complete) reduced in prologue.
// grid (A, B), block 192.
__global__ void k_av_fin() {
    const int a = blockIdx.x, b = blockIdx.y;
    const int tid = threadIdx.x;
    __shared__ float sInvS;
    if (tid < 32) {                              // prologue: weight sum
        float s = 0.f;
        #pragma unroll
        for (int j = 0; j < NSKT / 32; ++j) s += g_wsp[b][a][tid + j * 32];
        #pragma unroll
        for (int o = 16; o; o >>= 1) s += __shfl_down_sync(0xffffffffu, s, o);
        if (tid == 0) sInvS = 1.0f / s;
    }
    cudaGridDependencySynchronize();             // g_avpart ready
    cudaTriggerProgrammaticLaunchCompletion();
    float4 acc = make_float4(0.f, 0.f, 0.f, 0.f);
    #pragma unroll
    for (int s = 0; s < NSEG; ++s) {
        float4 p = g_avpart[b][s][a][tid];
        acc.x += p.x; acc.y += p.y; acc.z += p.z; acc.w += p.w;
    }
    __syncthreads();
    const float inv = sInvS;
    g_av[b][a][tid] = make_float4(acc.x * inv, acc.y * inv, acc.z * inv, acc.w * inv);
}

// ---------------------------------------------------------------
// Kernel 4: epilogue with inline stage-2 softmax.
// PDL: b2 softmax (pure input) computed before syncing on g_av.
// x[b,t,d] = sum_a softmax_a(b2[t,:])[a] * agent_v[b,a,d]
// (stage-2 softmax is q-independent by shift invariance: logits = q.m + b2,
//  q.m constant along a.)  grid (T/32, B), block 192. Writes x once (100MB).
__global__ void k_epilogue(const float* __restrict__ b2,
                           float4* __restrict__ out) {
    const int tb = blockIdx.x, b = blockIdx.y;
    const int tid = threadIdx.x;
    const int t0 = tb * 32;
    __shared__ __align__(16) float sp[32][8];   // padded
    if (tid < 32) {                              // prologue
        int t = t0 + tid;
        float vv[A];
        float mx = -1e30f;
        #pragma unroll
        for (int a = 0; a < A; ++a) { vv[a] = b2[t * A + a]; mx = fmaxf(mx, vv[a]); }
        float sum = 0.f;
        #pragma unroll
        for (int a = 0; a < A; ++a) { vv[a] = expf(vv[a] - mx); sum += vv[a]; }
        float inv = 1.0f / sum;
        #pragma unroll
        for (int a = 0; a < A; ++a) sp[tid][a] = vv[a] * inv;
    }
    cudaGridDependencySynchronize();             // g_av ready
    float4 av0 = g_av[b][0][tid], av1 = g_av[b][1][tid], av2 = g_av[b][2][tid],
           av3 = g_av[b][3][tid], av4 = g_av[b][4][tid];
    __syncthreads();
    float4* ob = out + ((size_t)b * T + t0) * D4 + tid;
    #pragma unroll 8
    for (int tt = 0; tt < 32; ++tt) {
        float4 pv = *(const float4*)&sp[tt][0];
        float  p4 = sp[tt][4];
        float4 r;
        r.x = pv.x*av0.x + pv.y*av1.x + pv.z*av2.x + pv.w*av3.x + p4*av4.x;
        r.y = pv.x*av0.y + pv.y*av1.y + pv.z*av2.y + pv.w*av3.y + p4*av4.y;
        r.z = pv.x*av0.z + pv.y*av1.z + pv.z*av2.z + pv.w*av3.z + p4*av4.z;
        r.w = pv.x*av0.w + pv.y*av1.w + pv.z*av2.w + pv.w*av3.w + p4*av4.w;
        ob[(size_t)tt * D4] = r;
    }
}

// ---------------------------------------------------------------
template <typename... Args>
static void launch_pdl(void (*kern)(Args...), dim3 grid, dim3 block,
                       bool pdl, Args... args) {
    cudaLaunchConfig_t cfg = {};
    cfg.gridDim = grid;
    cfg.blockDim = block;
    cfg.dynamicSmemBytes = 0;
    cfg.stream = 0;                              // legacy default stream
    cudaLaunchAttribute attr[1];
    attr[0].id = cudaLaunchAttributeProgrammaticStreamSerialization;
    attr[0].val.programmaticStreamSerializationAllowed = 1;
    cfg.attrs = attr;
    cfg.numAttrs = pdl ? 1 : 0;
    cudaLaunchKernelEx(&cfg, kern, args...);
}

extern "C" void kernel_launch(void* const* d_in, const int* in_sizes, int n_in,
                              void* d_out, int out_size) {
    const float* qkv  = (const float*)d_in[0];        // [3,B,T,D]
    const int*   mask = (const int*)d_in[1];          // [B,T]
    const float* b1   = (const float*)d_in[2];        // [A,T]
    const float* b2   = (const float*)d_in[3];        // [T,A]

    const float4* q = (const float4*)qkv;
    const float4* k = (const float4*)(qkv + (size_t)B * T * D);
    const float4* v = (const float4*)(qkv + 2 * (size_t)B * T * D);

    launch_pdl(k_mean_part, dim3(NSEG1, B), dim3(192), false, q, mask);
    launch_pdl(k_mean_fin, dim3((B * D4 + 255) / 256), dim3(256), true);
    launch_pdl(k_skt, dim3(NSKT, B), dim3(256), true, k, b1);
    launch_pdl(k_av_part, dim3(NSEG, B), dim3(192), true, v);
    launch_pdl(k_av_fin, dim3(A, B), dim3(192), true);
    launch_pdl(k_epilogue, dim3(T / 32, B), dim3(192), true, b2,
               (float4*)d_out);
}